// round 3
// baseline (speedup 1.0000x reference)
#include <cuda_runtime.h>
#include <cuda_bf16.h>
#include <cstdint>

// ============================================================
// BinaryMLP fused kernel for sm_103 virtual arch (NO tcgen05 —
// harness compiles compute_103, so "a"-features are unavailable).
// Portable mma.sync.m16n8k16 bf16 path, bf16 hi/lo splitting for
// fp32-grade accuracy. Fully fused: activations stay in registers
// across all 4 layers (D-fragment == A-fragment layout trick).
// Persistent CTAs, weights binarized once into smem per CTA.
// ============================================================

#define DIN   196
#define KPAD  208            // 13 k-steps of 16
#define HID   128
#define DOUT  10
#define TILE_M 128           // rows per CTA iteration (8 warps x 16)
#define NWARP 8
#define CTA_THREADS 256

// ---- smem byte offsets (dynamic) ----
// Weight fragment blocks: 32 bytes per (kstep, out_col) = 16 bf16 k-values
// arranged so lane q=(t%4) reads its (b0,b1) pair with one lds.v2.b32:
//   elem k -> ((k&7)>>1)*8 + ((k>>3)&1)*4 + (k&1)*2
#define SM_W1F  0                       // [13][128] blocks = 53248 B
#define SM_W2F  (SM_W1F + 13*128*32)    // [8][128]  blocks = 32768 B
#define SM_W3F  (SM_W2F + 8*128*32)
#define SM_W4HF (SM_W3F + 8*128*32)     // [8][16] blocks = 4096 B
#define SM_W4LF (SM_W4HF + 8*16*32)
#define SM_B1   (SM_W4LF + 8*16*32)     // 128 floats
#define SM_B2   (SM_B1 + 512)
#define SM_B3   (SM_B2 + 512)
#define SM_B4   (SM_B3 + 512)           // 16 floats (padded)
#define SM_TOTAL (SM_B4 + 64)

__device__ __forceinline__ int frag_off(int k) {
    return ((k & 7) >> 1) * 8 + ((k >> 3) & 1) * 4 + (k & 1) * 2;
}

// mma.sync m16n8k16 row.col f32 <- bf16 x bf16 + f32 (sm_80+, OK on compute_103)
__device__ __forceinline__ void mma16816(float* d, const uint32_t* a, const uint32_t* b) {
    asm volatile(
        "mma.sync.aligned.m16n8k16.row.col.f32.bf16.bf16.f32 "
        "{%0,%1,%2,%3},{%4,%5,%6,%7},{%8,%9},{%0,%1,%2,%3};"
        : "+f"(d[0]), "+f"(d[1]), "+f"(d[2]), "+f"(d[3])
        : "r"(a[0]), "r"(a[1]), "r"(a[2]), "r"(a[3]), "r"(b[0]), "r"(b[1]));
}

// split fp32 pair -> (hi, lo) bf16x2 words (v0 in low half)
__device__ __forceinline__ void split2(float v0, float v1, uint32_t& hw, uint32_t& lw) {
    __nv_bfloat16 h0 = __float2bfloat16(v0), h1 = __float2bfloat16(v1);
    __nv_bfloat16 l0 = __float2bfloat16(v0 - __bfloat162float(h0));
    __nv_bfloat16 l1 = __float2bfloat16(v1 - __bfloat162float(h1));
    hw = ((uint32_t)__bfloat16_as_ushort(h1) << 16) | (uint32_t)__bfloat16_as_ushort(h0);
    lw = ((uint32_t)__bfloat16_as_ushort(l1) << 16) | (uint32_t)__bfloat16_as_ushort(l0);
}

// D fragments (16 x n8, fp32) -> +bias, ReLU, hi/lo split -> A fragments (8 ksteps)
__device__ __forceinline__ void epilogue_hidden(
    const float D[16][4], const float* bias, int q,
    uint32_t Ah[8][4], uint32_t Al[8][4])
{
    #pragma unroll
    for (int kk = 0; kk < 8; kk++) {
        const float* bp = bias + 16 * kk + q * 2;
        float2 b0 = *(const float2*)bp;
        float2 b1 = *(const float2*)(bp + 8);
        int f0 = 2 * kk, f1 = f0 + 1;
        float v0 = fmaxf(D[f0][0] + b0.x, 0.f), v1 = fmaxf(D[f0][1] + b0.y, 0.f);
        float v2 = fmaxf(D[f0][2] + b0.x, 0.f), v3 = fmaxf(D[f0][3] + b0.y, 0.f);
        split2(v0, v1, Ah[kk][0], Al[kk][0]);
        split2(v2, v3, Ah[kk][1], Al[kk][1]);
        float w0 = fmaxf(D[f1][0] + b1.x, 0.f), w1 = fmaxf(D[f1][1] + b1.y, 0.f);
        float w2 = fmaxf(D[f1][2] + b1.x, 0.f), w3 = fmaxf(D[f1][3] + b1.y, 0.f);
        split2(w0, w1, Ah[kk][2], Al[kk][2]);
        split2(w2, w3, Ah[kk][3], Al[kk][3]);
    }
}

__global__ void __launch_bounds__(CTA_THREADS, 1) bmlp_kernel(
    const float* __restrict__ x,
    const float* __restrict__ W1, const float* __restrict__ b1,
    const float* __restrict__ W2, const float* __restrict__ b2,
    const float* __restrict__ W3, const float* __restrict__ b3,
    const float* __restrict__ W4, const float* __restrict__ b4,
    float* __restrict__ out, int n_tiles)
{
    extern __shared__ char smem[];
    const int tid = threadIdx.x;
    const int lane = tid & 31;
    const int warp = tid >> 5;
    const int r = lane >> 2;      // row-in-fragment / B n-col selector
    const int q = lane & 3;       // k-pair selector

    // ---------------- prologue: weights -> smem fragment layout ----------------
    const unsigned short POS = 0x3F80u;   // bf16 +1.0
    const unsigned short NEG = 0xBF80u;   // bf16 -1.0

    for (int i = tid; i < HID * KPAD; i += CTA_THREADS) {
        int n = i / KPAD, k = i - n * KPAD;
        unsigned short s = 0;
        if (k < DIN) {
            float w = W1[n * DIN + k];
            s = (w > 0.f) ? POS : ((w < 0.f) ? NEG : (unsigned short)0);
        }
        *(unsigned short*)(smem + SM_W1F + ((k >> 4) * HID + n) * 32 + frag_off(k)) = s;
    }
    for (int i = tid; i < HID * HID; i += CTA_THREADS) {
        int n = i >> 7, k = i & 127;
        float w2 = W2[i], w3 = W3[i];
        unsigned short s2 = (w2 > 0.f) ? POS : ((w2 < 0.f) ? NEG : (unsigned short)0);
        unsigned short s3 = (w3 > 0.f) ? POS : ((w3 < 0.f) ? NEG : (unsigned short)0);
        int ofs = ((k >> 4) * HID + n) * 32 + frag_off(k);
        *(unsigned short*)(smem + SM_W2F + ofs) = s2;
        *(unsigned short*)(smem + SM_W3F + ofs) = s3;
    }
    for (int i = tid; i < 16 * HID; i += CTA_THREADS) {
        int n = i >> 7, k = i & 127;
        float w = (n < DOUT) ? W4[n * HID + k] : 0.f;
        __nv_bfloat16 h = __float2bfloat16(w);
        __nv_bfloat16 l = __float2bfloat16(w - __bfloat162float(h));
        int ofs = ((k >> 4) * 16 + n) * 32 + frag_off(k);
        *(unsigned short*)(smem + SM_W4HF + ofs) = __bfloat16_as_ushort(h);
        *(unsigned short*)(smem + SM_W4LF + ofs) = __bfloat16_as_ushort(l);
    }
    if (tid < HID) {
        ((float*)(smem + SM_B1))[tid] = b1[tid];
        ((float*)(smem + SM_B2))[tid] = b2[tid];
        ((float*)(smem + SM_B3))[tid] = b3[tid];
    }
    if (tid < 16) ((float*)(smem + SM_B4))[tid] = (tid < DOUT) ? b4[tid] : 0.f;
    __syncthreads();
    // After this point: zero barriers. Each warp is fully independent.

    const float* b1s = (const float*)(smem + SM_B1);
    const float* b2s = (const float*)(smem + SM_B2);
    const float* b3s = (const float*)(smem + SM_B3);
    const float* b4s = (const float*)(smem + SM_B4);

    for (int t = blockIdx.x; t < n_tiles; t += gridDim.x) {
        const size_t row0 = (size_t)t * TILE_M + warp * 16 + r;
        const float* x0 = x + row0 * DIN;
        const float* x8 = x0 + (size_t)8 * DIN;

        float D[16][4];
        #pragma unroll
        for (int f = 0; f < 16; f++)
            #pragma unroll
            for (int j = 0; j < 4; j++) D[f][j] = 0.f;

        // ---- layer 1: K = 208 (pad), A from global x, hi/lo ----
        #pragma unroll
        for (int kk = 0; kk < 13; kk++) {
            int c0 = kk * 16 + q * 2;
            int c1 = c0 + 8;
            float2 z = make_float2(0.f, 0.f);
            float2 p0 = (c0 < DIN) ? *(const float2*)(x0 + c0) : z;
            float2 p1 = (c0 < DIN) ? *(const float2*)(x8 + c0) : z;
            float2 p2 = (c1 < DIN) ? *(const float2*)(x0 + c1) : z;
            float2 p3 = (c1 < DIN) ? *(const float2*)(x8 + c1) : z;
            uint32_t ah[4], al[4];
            split2(p0.x, p0.y, ah[0], al[0]);
            split2(p1.x, p1.y, ah[1], al[1]);
            split2(p2.x, p2.y, ah[2], al[2]);
            split2(p3.x, p3.y, ah[3], al[3]);
            #pragma unroll
            for (int n = 0; n < 16; n++) {
                uint2 bb = *(const uint2*)(smem + SM_W1F + ((kk * HID + n * 8 + r) << 5) + q * 8);
                uint32_t b[2] = { bb.x, bb.y };
                mma16816(D[n], ah, b);
                mma16816(D[n], al, b);
            }
        }

        uint32_t Ah[8][4], Al[8][4];
        epilogue_hidden(D, b1s, q, Ah, Al);

        // ---- layer 2 ----
        #pragma unroll
        for (int f = 0; f < 16; f++)
            #pragma unroll
            for (int j = 0; j < 4; j++) D[f][j] = 0.f;
        #pragma unroll
        for (int kk = 0; kk < 8; kk++) {
            #pragma unroll
            for (int n = 0; n < 16; n++) {
                uint2 bb = *(const uint2*)(smem + SM_W2F + ((kk * HID + n * 8 + r) << 5) + q * 8);
                uint32_t b[2] = { bb.x, bb.y };
                mma16816(D[n], Ah[kk], b);
                mma16816(D[n], Al[kk], b);
            }
        }
        epilogue_hidden(D, b2s, q, Ah, Al);

        // ---- layer 3 ----
        #pragma unroll
        for (int f = 0; f < 16; f++)
            #pragma unroll
            for (int j = 0; j < 4; j++) D[f][j] = 0.f;
        #pragma unroll
        for (int kk = 0; kk < 8; kk++) {
            #pragma unroll
            for (int n = 0; n < 16; n++) {
                uint2 bb = *(const uint2*)(smem + SM_W3F + ((kk * HID + n * 8 + r) << 5) + q * 8);
                uint32_t b[2] = { bb.x, bb.y };
                mma16816(D[n], Ah[kk], b);
                mma16816(D[n], Al[kk], b);
            }
        }
        epilogue_hidden(D, b3s, q, Ah, Al);

        // ---- layer 4 (head, full precision W4 as hi+lo; drop lo*lo) ----
        float D4[2][4];
        #pragma unroll
        for (int f = 0; f < 2; f++)
            #pragma unroll
            for (int j = 0; j < 4; j++) D4[f][j] = 0.f;
        #pragma unroll
        for (int kk = 0; kk < 8; kk++) {
            #pragma unroll
            for (int n = 0; n < 2; n++) {
                int ofs = ((kk * 16 + n * 8 + r) << 5) + q * 8;
                uint2 bhw = *(const uint2*)(smem + SM_W4HF + ofs);
                uint2 blw = *(const uint2*)(smem + SM_W4LF + ofs);
                uint32_t bh[2] = { bhw.x, bhw.y };
                uint32_t bl[2] = { blw.x, blw.y };
                mma16816(D4[n], Ah[kk], bh);
                mma16816(D4[n], Al[kk], bh);
                mma16816(D4[n], Ah[kk], bl);
            }
        }

        // ---- output: cols q*2, q*2+1 (frag 0); cols 8,9 (frag 1, q==0) ----
        {
            float* o0 = out + row0 * DOUT;
            float* o8 = o0 + (size_t)8 * DOUT;
            int c = q * 2;
            float2 bb = *(const float2*)(b4s + c);
            float2 v0 = make_float2(D4[0][0] + bb.x, D4[0][1] + bb.y);
            float2 v8 = make_float2(D4[0][2] + bb.x, D4[0][3] + bb.y);
            *(float2*)(o0 + c) = v0;
            *(float2*)(o8 + c) = v8;
            if (q == 0) {
                float2 b8 = *(const float2*)(b4s + 8);
                float2 u0 = make_float2(D4[1][0] + b8.x, D4[1][1] + b8.y);
                float2 u8 = make_float2(D4[1][2] + b8.x, D4[1][3] + b8.y);
                *(float2*)(o0 + 8) = u0;
                *(float2*)(o8 + 8) = u8;
            }
        }
    }
}

extern "C" void kernel_launch(void* const* d_in, const int* in_sizes, int n_in,
                              void* d_out, int out_size) {
    const float* x  = (const float*)d_in[0];
    const float* W1 = (const float*)d_in[1];
    const float* b1 = (const float*)d_in[2];
    const float* W2 = (const float*)d_in[3];
    const float* b2 = (const float*)d_in[4];
    const float* W3 = (const float*)d_in[5];
    const float* b3 = (const float*)d_in[6];
    const float* W4 = (const float*)d_in[7];
    const float* b4 = (const float*)d_in[8];
    float* out = (float*)d_out;

    int B = in_sizes[0] / DIN;
    int n_tiles = B / TILE_M;

    static int configured = 0;
    if (!configured) {
        cudaFuncSetAttribute(bmlp_kernel, cudaFuncAttributeMaxDynamicSharedMemorySize, SM_TOTAL);
        configured = 1;
    }

    int grid = n_tiles < 152 ? n_tiles : 152;
    bmlp_kernel<<<grid, CTA_THREADS, SM_TOTAL>>>(x, W1, b1, W2, b2, W3, b3, W4, b4, out, n_tiles);
}

// round 4
// speedup vs baseline: 1.8570x; 1.8570x over previous
#include <cuda_runtime.h>
#include <cuda_fp16.h>
#include <cstdint>

// ============================================================
// BinaryMLP fused kernel (sm_103 virtual arch — portable mma.sync).
// R4: fp16 single-pass (binary weights exact in fp16), sign-byte
// compressed weights in smem (1B/weight, PRMT-expanded to fp16
// fragments: fp16 +-1 == signbyte<<8), 12 independent warps/CTA.
// Activations live in registers across all 4 layers.
// ============================================================

#define DIN   196
#define KPAD  208            // 13 k-steps of 16
#define HID   128
#define DOUT  10
#define NWARP 12
#define CTA_THREADS (NWARP * 32)

// ---- smem byte offsets ----
// Sign blocks: per (kstep, nblock) 128 B: lane (r*4+q) word = 4 sign bytes
//   [s(2q), s(2q+1), s(2q+8), s(2q+9)] for out-col n = nb*8 + r.
#define SM_W1S  0                        // [13][16] * 128 B = 26624
#define SM_W2S  (SM_W1S + 13*16*128)     // [8][16] * 128 = 16384
#define SM_W3S  (SM_W2S + 8*16*128)
#define SM_W4HF (SM_W3S + 8*16*128)      // fp16 frag blocks [8][16]*32 = 4096
#define SM_W4LF (SM_W4HF + 8*16*32)
#define SM_B1   (SM_W4LF + 8*16*32)
#define SM_B2   (SM_B1 + 512)
#define SM_B3   (SM_B2 + 512)
#define SM_B4   (SM_B3 + 512)
#define SM_TOTAL (SM_B4 + 64)

// fp16-frag byte offset within a 32B block (for W4 real-valued head)
__device__ __forceinline__ int frag_off(int k) {
    return ((k & 7) >> 1) * 8 + ((k >> 3) & 1) * 4 + (k & 1) * 2;
}
// sign-byte offset within a 128B block
__device__ __forceinline__ int sgn_off(int n, int k) {
    return ((n & 7) * 4 + ((k & 7) >> 1)) * 4 + ((k >> 3) & 1) * 2 + (k & 1);
}

// mma.sync m16n8k16 row.col f32 <- f16 x f16 + f32
__device__ __forceinline__ void mma16816(float* d, const uint32_t* a, const uint32_t* b) {
    asm volatile(
        "mma.sync.aligned.m16n8k16.row.col.f32.f16.f16.f32 "
        "{%0,%1,%2,%3},{%4,%5,%6,%7},{%8,%9},{%0,%1,%2,%3};"
        : "+f"(d[0]), "+f"(d[1]), "+f"(d[2]), "+f"(d[3])
        : "r"(a[0]), "r"(a[1]), "r"(a[2]), "r"(a[3]), "r"(b[0]), "r"(b[1]));
}

__device__ __forceinline__ uint32_t h2pack(float a, float b) {
    __half2 h = __floats2half2_rn(a, b);          // low = a, high = b
    return *reinterpret_cast<uint32_t*>(&h);
}

// D fragments -> +bias, ReLU, fp16 pack -> A fragments for next layer
__device__ __forceinline__ void epilogue_hidden(
    const float D[16][4], const float* bias, int q, uint32_t Ah[8][4])
{
    #pragma unroll
    for (int kk = 0; kk < 8; kk++) {
        const float* bp = bias + 16 * kk + q * 2;
        float2 b0 = *(const float2*)bp;
        float2 b1 = *(const float2*)(bp + 8);
        int f0 = 2 * kk, f1 = f0 + 1;
        Ah[kk][0] = h2pack(fmaxf(D[f0][0] + b0.x, 0.f), fmaxf(D[f0][1] + b0.y, 0.f));
        Ah[kk][1] = h2pack(fmaxf(D[f0][2] + b0.x, 0.f), fmaxf(D[f0][3] + b0.y, 0.f));
        Ah[kk][2] = h2pack(fmaxf(D[f1][0] + b1.x, 0.f), fmaxf(D[f1][1] + b1.y, 0.f));
        Ah[kk][3] = h2pack(fmaxf(D[f1][2] + b1.x, 0.f), fmaxf(D[f1][3] + b1.y, 0.f));
    }
}

__global__ void __launch_bounds__(CTA_THREADS, 1) bmlp_kernel(
    const float* __restrict__ x,
    const float* __restrict__ W1, const float* __restrict__ b1,
    const float* __restrict__ W2, const float* __restrict__ b2,
    const float* __restrict__ W3, const float* __restrict__ b3,
    const float* __restrict__ W4, const float* __restrict__ b4,
    float* __restrict__ out, int n_chunks)
{
    extern __shared__ char smem[];
    const int tid = threadIdx.x;
    const int lane = tid & 31;
    const int warp = tid >> 5;
    const int r = lane >> 2;
    const int q = lane & 3;

    // ---------------- prologue: weights -> smem ----------------
    for (int i = tid; i < HID * KPAD; i += CTA_THREADS) {
        int n = i / KPAD, k = i - n * KPAD;
        unsigned char s = 0;
        if (k < DIN) {
            float w = W1[n * DIN + k];
            s = (w > 0.f) ? 0x3Cu : ((w < 0.f) ? 0xBCu : 0u);
        }
        smem[SM_W1S + ((k >> 4) * 16 + (n >> 3)) * 128 + sgn_off(n, k)] = s;
    }
    for (int i = tid; i < HID * HID; i += CTA_THREADS) {
        int n = i >> 7, k = i & 127;
        float w2 = W2[i], w3 = W3[i];
        unsigned char s2 = (w2 > 0.f) ? 0x3Cu : ((w2 < 0.f) ? 0xBCu : 0u);
        unsigned char s3 = (w3 > 0.f) ? 0x3Cu : ((w3 < 0.f) ? 0xBCu : 0u);
        int ofs = ((k >> 4) * 16 + (n >> 3)) * 128 + sgn_off(n, k);
        smem[SM_W2S + ofs] = s2;
        smem[SM_W3S + ofs] = s3;
    }
    for (int i = tid; i < 16 * HID; i += CTA_THREADS) {
        int n = i >> 7, k = i & 127;
        float w = (n < DOUT) ? W4[n * HID + k] : 0.f;
        __half h = __float2half_rn(w);
        __half l = __float2half_rn(w - __half2float(h));
        int ofs = ((k >> 4) * 16 + n) * 32 + frag_off(k);
        *(unsigned short*)(smem + SM_W4HF + ofs) = __half_as_ushort(h);
        *(unsigned short*)(smem + SM_W4LF + ofs) = __half_as_ushort(l);
    }
    if (tid < HID) {
        ((float*)(smem + SM_B1))[tid] = b1[tid];
        ((float*)(smem + SM_B2))[tid] = b2[tid];
        ((float*)(smem + SM_B3))[tid] = b3[tid];
    }
    if (tid < 16) ((float*)(smem + SM_B4))[tid] = (tid < DOUT) ? b4[tid] : 0.f;
    __syncthreads();
    // Zero barriers after this point: warps fully independent.

    const float* b1s = (const float*)(smem + SM_B1);
    const float* b2s = (const float*)(smem + SM_B2);
    const float* b3s = (const float*)(smem + SM_B3);
    const float* b4s = (const float*)(smem + SM_B4);

    const int wstride = gridDim.x * NWARP;
    for (int c = blockIdx.x * NWARP + warp; c < n_chunks; c += wstride) {
        const size_t row0 = (size_t)c * 16 + r;
        const float* x0 = x + row0 * DIN;
        const float* x8 = x0 + (size_t)8 * DIN;

        float D[16][4];
        #pragma unroll
        for (int f = 0; f < 16; f++)
            #pragma unroll
            for (int j = 0; j < 4; j++) D[f][j] = 0.f;

        // ---- layer 1 (K padded to 208) ----
        #pragma unroll
        for (int kk = 0; kk < 13; kk++) {
            int c0 = kk * 16 + q * 2;
            int c1 = c0 + 8;
            float2 z = make_float2(0.f, 0.f);
            float2 p0 = (c0 < DIN) ? *(const float2*)(x0 + c0) : z;
            float2 p1 = (c0 < DIN) ? *(const float2*)(x8 + c0) : z;
            float2 p2 = (c1 < DIN) ? *(const float2*)(x0 + c1) : z;
            float2 p3 = (c1 < DIN) ? *(const float2*)(x8 + c1) : z;
            uint32_t a[4];
            a[0] = h2pack(p0.x, p0.y);
            a[1] = h2pack(p1.x, p1.y);
            a[2] = h2pack(p2.x, p2.y);
            a[3] = h2pack(p3.x, p3.y);
            #pragma unroll
            for (int n = 0; n < 16; n++) {
                uint32_t w = *(const uint32_t*)(smem + SM_W1S + ((kk * 16 + n) << 7) + lane * 4);
                uint32_t b[2] = { __byte_perm(w, 0, 0x1404), __byte_perm(w, 0, 0x3424) };
                mma16816(D[n], a, b);
            }
        }

        uint32_t Ah[8][4];
        epilogue_hidden(D, b1s, q, Ah);

        // ---- layer 2 ----
        #pragma unroll
        for (int f = 0; f < 16; f++)
            #pragma unroll
            for (int j = 0; j < 4; j++) D[f][j] = 0.f;
        #pragma unroll
        for (int kk = 0; kk < 8; kk++) {
            #pragma unroll
            for (int n = 0; n < 16; n++) {
                uint32_t w = *(const uint32_t*)(smem + SM_W2S + ((kk * 16 + n) << 7) + lane * 4);
                uint32_t b[2] = { __byte_perm(w, 0, 0x1404), __byte_perm(w, 0, 0x3424) };
                mma16816(D[n], Ah[kk], b);
            }
        }
        epilogue_hidden(D, b2s, q, Ah);

        // ---- layer 3 ----
        #pragma unroll
        for (int f = 0; f < 16; f++)
            #pragma unroll
            for (int j = 0; j < 4; j++) D[f][j] = 0.f;
        #pragma unroll
        for (int kk = 0; kk < 8; kk++) {
            #pragma unroll
            for (int n = 0; n < 16; n++) {
                uint32_t w = *(const uint32_t*)(smem + SM_W3S + ((kk * 16 + n) << 7) + lane * 4);
                uint32_t b[2] = { __byte_perm(w, 0, 0x1404), __byte_perm(w, 0, 0x3424) };
                mma16816(D[n], Ah[kk], b);
            }
        }
        epilogue_hidden(D, b3s, q, Ah);

        // ---- layer 4 (head; W4 = hi + lo fp16, both applied) ----
        float D4[2][4];
        #pragma unroll
        for (int f = 0; f < 2; f++)
            #pragma unroll
            for (int j = 0; j < 4; j++) D4[f][j] = 0.f;
        #pragma unroll
        for (int kk = 0; kk < 8; kk++) {
            #pragma unroll
            for (int n = 0; n < 2; n++) {
                int ofs = ((kk * 16 + n * 8 + r) << 5) + q * 8;
                uint2 bhw = *(const uint2*)(smem + SM_W4HF + ofs);
                uint2 blw = *(const uint2*)(smem + SM_W4LF + ofs);
                uint32_t bh[2] = { bhw.x, bhw.y };
                uint32_t bl[2] = { blw.x, blw.y };
                mma16816(D4[n], Ah[kk], bh);
                mma16816(D4[n], Ah[kk], bl);
            }
        }

        // ---- output ----
        {
            float* o0 = out + row0 * DOUT;
            float* o8 = o0 + (size_t)8 * DOUT;
            int cc = q * 2;
            float2 bb = *(const float2*)(b4s + cc);
            *(float2*)(o0 + cc) = make_float2(D4[0][0] + bb.x, D4[0][1] + bb.y);
            *(float2*)(o8 + cc) = make_float2(D4[0][2] + bb.x, D4[0][3] + bb.y);
            if (q == 0) {
                float2 b8 = *(const float2*)(b4s + 8);
                *(float2*)(o0 + 8) = make_float2(D4[1][0] + b8.x, D4[1][1] + b8.y);
                *(float2*)(o8 + 8) = make_float2(D4[1][2] + b8.x, D4[1][3] + b8.y);
            }
        }
    }
}

extern "C" void kernel_launch(void* const* d_in, const int* in_sizes, int n_in,
                              void* d_out, int out_size) {
    const float* x  = (const float*)d_in[0];
    const float* W1 = (const float*)d_in[1];
    const float* b1 = (const float*)d_in[2];
    const float* W2 = (const float*)d_in[3];
    const float* b2 = (const float*)d_in[4];
    const float* W3 = (const float*)d_in[5];
    const float* b3 = (const float*)d_in[6];
    const float* W4 = (const float*)d_in[7];
    const float* b4 = (const float*)d_in[8];
    float* out = (float*)d_out;

    int B = in_sizes[0] / DIN;
    int n_chunks = B / 16;

    static int configured = 0;
    if (!configured) {
        cudaFuncSetAttribute(bmlp_kernel, cudaFuncAttributeMaxDynamicSharedMemorySize, SM_TOTAL);
        configured = 1;
    }

    int grid = 152;
    int max_grid = (n_chunks + NWARP - 1) / NWARP;
    if (grid > max_grid) grid = max_grid;
    bmlp_kernel<<<grid, CTA_THREADS, SM_TOTAL>>>(x, W1, b1, W2, b2, W3, b3, W4, b4, out, n_chunks);
}

// round 5
// speedup vs baseline: 2.0429x; 1.1001x over previous
#include <cuda_runtime.h>
#include <cuda_fp16.h>
#include <cstdint>

// ============================================================
// BinaryMLP fused kernel (sm_103 virtual arch — portable mma.sync).
// R5: 32 rows/warp (B-fragment reuse across two 16-row halves),
// lds.128 sign loads covering 4 n-blocks, PRMT expansion shared.
// Per-HMMA overhead: 0.5 smem wavefront + 1 PRMT (was 1 + 2).
// 8 warps/CTA (register budget), fp16 single-pass, fully fused.
// ============================================================

#define DIN   196
#define KPAD  208
#define HID   128
#define DOUT  10
#define NWARP 8
#define CTA_THREADS (NWARP * 32)

// ---- smem layout ----
// Sign groups: per (kstep, ngroup of 4 n-blocks): 512 B.
//   lane reads uint4 at lane*16; word j = signs for n-block ng*4+j.
#define SM_W1S  0                        // 13*4*512 = 26624
#define SM_W2S  (SM_W1S + 13*4*512)      // 8*4*512 = 16384
#define SM_W3S  (SM_W2S + 8*4*512)
#define SM_W4HF (SM_W3S + 8*4*512)       // fp16 frag blocks [8][16]*32 = 4096
#define SM_W4LF (SM_W4HF + 8*16*32)
#define SM_B1   (SM_W4LF + 8*16*32)
#define SM_B2   (SM_B1 + 512)
#define SM_B3   (SM_B2 + 512)
#define SM_B4   (SM_B3 + 512)
#define SM_TOTAL (SM_B4 + 64)

__device__ __forceinline__ int frag_off(int k) {
    return ((k & 7) >> 1) * 8 + ((k >> 3) & 1) * 4 + (k & 1) * 2;
}
// sign byte address for (out-col n, k) in grouped layout
__device__ __forceinline__ int sgn_addr(int n, int k) {
    int kk = k >> 4, nb = n >> 3, ng = nb >> 2, j = nb & 3;
    return ((kk * 4 + ng) << 9) + (((n & 7) * 4 + ((k & 7) >> 1)) << 4)
         + (j << 2) + (((k >> 3) & 1) << 1) + (k & 1);
}

__device__ __forceinline__ void mma16816(float* d, const uint32_t* a, const uint32_t* b) {
    asm volatile(
        "mma.sync.aligned.m16n8k16.row.col.f32.f16.f16.f32 "
        "{%0,%1,%2,%3},{%4,%5,%6,%7},{%8,%9},{%0,%1,%2,%3};"
        : "+f"(d[0]), "+f"(d[1]), "+f"(d[2]), "+f"(d[3])
        : "r"(a[0]), "r"(a[1]), "r"(a[2]), "r"(a[3]), "r"(b[0]), "r"(b[1]));
}

__device__ __forceinline__ uint32_t h2pack(float a, float b) {
    __half2 h = __floats2half2_rn(a, b);
    return *reinterpret_cast<uint32_t*>(&h);
}

// D -> +bias, ReLU, fp16 -> A fragments
__device__ __forceinline__ void epilogue_hidden(
    const float D[16][4], const float* bias, int q, uint32_t Ah[8][4])
{
    #pragma unroll
    for (int kk = 0; kk < 8; kk++) {
        const float* bp = bias + 16 * kk + q * 2;
        float2 b0 = *(const float2*)bp;
        float2 b1 = *(const float2*)(bp + 8);
        int f0 = 2 * kk, f1 = f0 + 1;
        Ah[kk][0] = h2pack(fmaxf(D[f0][0] + b0.x, 0.f), fmaxf(D[f0][1] + b0.y, 0.f));
        Ah[kk][1] = h2pack(fmaxf(D[f0][2] + b0.x, 0.f), fmaxf(D[f0][3] + b0.y, 0.f));
        Ah[kk][2] = h2pack(fmaxf(D[f1][0] + b1.x, 0.f), fmaxf(D[f1][1] + b1.y, 0.f));
        Ah[kk][3] = h2pack(fmaxf(D[f1][2] + b1.x, 0.f), fmaxf(D[f1][3] + b1.y, 0.f));
    }
}

__global__ void __launch_bounds__(CTA_THREADS, 1) bmlp_kernel(
    const float* __restrict__ x,
    const float* __restrict__ W1, const float* __restrict__ b1,
    const float* __restrict__ W2, const float* __restrict__ b2,
    const float* __restrict__ W3, const float* __restrict__ b3,
    const float* __restrict__ W4, const float* __restrict__ b4,
    float* __restrict__ out, int n_units)
{
    extern __shared__ char smem[];
    const int tid = threadIdx.x;
    const int lane = tid & 31;
    const int warp = tid >> 5;
    const int r = lane >> 2;
    const int q = lane & 3;

    // ---------------- prologue: weights -> smem ----------------
    for (int i = tid; i < HID * KPAD; i += CTA_THREADS) {
        int n = i / KPAD, k = i - n * KPAD;
        unsigned char s = 0;
        if (k < DIN) {
            float w = W1[n * DIN + k];
            s = (w > 0.f) ? 0x3Cu : ((w < 0.f) ? 0xBCu : 0u);
        }
        smem[SM_W1S + sgn_addr(n, k)] = s;
    }
    for (int i = tid; i < HID * HID; i += CTA_THREADS) {
        int n = i >> 7, k = i & 127;
        float w2 = W2[i], w3 = W3[i];
        unsigned char s2 = (w2 > 0.f) ? 0x3Cu : ((w2 < 0.f) ? 0xBCu : 0u);
        unsigned char s3 = (w3 > 0.f) ? 0x3Cu : ((w3 < 0.f) ? 0xBCu : 0u);
        int a = sgn_addr(n, k);
        smem[SM_W2S + a] = s2;
        smem[SM_W3S + a] = s3;
    }
    for (int i = tid; i < 16 * HID; i += CTA_THREADS) {
        int n = i >> 7, k = i & 127;
        float w = (n < DOUT) ? W4[n * HID + k] : 0.f;
        __half h = __float2half_rn(w);
        __half l = __float2half_rn(w - __half2float(h));
        int ofs = ((k >> 4) * 16 + n) * 32 + frag_off(k);
        *(unsigned short*)(smem + SM_W4HF + ofs) = __half_as_ushort(h);
        *(unsigned short*)(smem + SM_W4LF + ofs) = __half_as_ushort(l);
    }
    if (tid < HID) {
        ((float*)(smem + SM_B1))[tid] = b1[tid];
        ((float*)(smem + SM_B2))[tid] = b2[tid];
        ((float*)(smem + SM_B3))[tid] = b3[tid];
    }
    if (tid < 16) ((float*)(smem + SM_B4))[tid] = (tid < DOUT) ? b4[tid] : 0.f;
    __syncthreads();
    // Zero barriers after this point.

    const float* b1s = (const float*)(smem + SM_B1);
    const float* b2s = (const float*)(smem + SM_B2);
    const float* b3s = (const float*)(smem + SM_B3);
    const float* b4s = (const float*)(smem + SM_B4);

    const int wstride = gridDim.x * NWARP;
    for (int c = blockIdx.x * NWARP + warp; c < n_units; c += wstride) {
        const size_t row0 = (size_t)c * 32 + r;
        const float* xa = x + row0 * DIN;           // half0 rows r, r+8
        const float* xb = xa + (size_t)8 * DIN;
        const float* xc = xa + (size_t)16 * DIN;    // half1 rows r+16, r+24
        const float* xd = xa + (size_t)24 * DIN;

        float D0[16][4], D1[16][4];
        #pragma unroll
        for (int f = 0; f < 16; f++)
            #pragma unroll
            for (int j = 0; j < 4; j++) { D0[f][j] = 0.f; D1[f][j] = 0.f; }

        // ---- layer 1 (K padded to 208) ----
        #pragma unroll
        for (int kk = 0; kk < 13; kk++) {
            int c0 = kk * 16 + q * 2;
            int c1 = c0 + 8;
            float2 z = make_float2(0.f, 0.f);
            float2 pa0 = (c0 < DIN) ? *(const float2*)(xa + c0) : z;
            float2 pb0 = (c0 < DIN) ? *(const float2*)(xb + c0) : z;
            float2 pc0 = (c0 < DIN) ? *(const float2*)(xc + c0) : z;
            float2 pd0 = (c0 < DIN) ? *(const float2*)(xd + c0) : z;
            float2 pa1 = (c1 < DIN) ? *(const float2*)(xa + c1) : z;
            float2 pb1 = (c1 < DIN) ? *(const float2*)(xb + c1) : z;
            float2 pc1 = (c1 < DIN) ? *(const float2*)(xc + c1) : z;
            float2 pd1 = (c1 < DIN) ? *(const float2*)(xd + c1) : z;
            uint32_t a0[4], a1[4];
            a0[0] = h2pack(pa0.x, pa0.y); a0[1] = h2pack(pb0.x, pb0.y);
            a0[2] = h2pack(pa1.x, pa1.y); a0[3] = h2pack(pb1.x, pb1.y);
            a1[0] = h2pack(pc0.x, pc0.y); a1[1] = h2pack(pd0.x, pd0.y);
            a1[2] = h2pack(pc1.x, pc1.y); a1[3] = h2pack(pd1.x, pd1.y);
            #pragma unroll
            for (int ng = 0; ng < 4; ng++) {
                uint4 w = *(const uint4*)(smem + SM_W1S + (((kk * 4 + ng) << 9) + lane * 16));
                uint32_t b0[2] = { __byte_perm(w.x, 0, 0x1404), __byte_perm(w.x, 0, 0x3424) };
                uint32_t b1r[2] = { __byte_perm(w.y, 0, 0x1404), __byte_perm(w.y, 0, 0x3424) };
                uint32_t b2r[2] = { __byte_perm(w.z, 0, 0x1404), __byte_perm(w.z, 0, 0x3424) };
                uint32_t b3r[2] = { __byte_perm(w.w, 0, 0x1404), __byte_perm(w.w, 0, 0x3424) };
                mma16816(D0[ng * 4 + 0], a0, b0);  mma16816(D1[ng * 4 + 0], a1, b0);
                mma16816(D0[ng * 4 + 1], a0, b1r); mma16816(D1[ng * 4 + 1], a1, b1r);
                mma16816(D0[ng * 4 + 2], a0, b2r); mma16816(D1[ng * 4 + 2], a1, b2r);
                mma16816(D0[ng * 4 + 3], a0, b3r); mma16816(D1[ng * 4 + 3], a1, b3r);
            }
        }

        uint32_t Ah0[8][4], Ah1[8][4];
        epilogue_hidden(D0, b1s, q, Ah0);
        epilogue_hidden(D1, b1s, q, Ah1);

        // ---- layers 2 and 3 ----
        #pragma unroll
        for (int L = 0; L < 2; L++) {
            const char* Ws = (L == 0) ? (smem + SM_W2S) : (smem + SM_W3S);
            const float* bs = (L == 0) ? b2s : b3s;
            #pragma unroll
            for (int f = 0; f < 16; f++)
                #pragma unroll
                for (int j = 0; j < 4; j++) { D0[f][j] = 0.f; D1[f][j] = 0.f; }
            #pragma unroll
            for (int kk = 0; kk < 8; kk++) {
                #pragma unroll
                for (int ng = 0; ng < 4; ng++) {
                    uint4 w = *(const uint4*)(Ws + (((kk * 4 + ng) << 9) + lane * 16));
                    uint32_t b0[2] = { __byte_perm(w.x, 0, 0x1404), __byte_perm(w.x, 0, 0x3424) };
                    uint32_t b1r[2] = { __byte_perm(w.y, 0, 0x1404), __byte_perm(w.y, 0, 0x3424) };
                    uint32_t b2r[2] = { __byte_perm(w.z, 0, 0x1404), __byte_perm(w.z, 0, 0x3424) };
                    uint32_t b3r[2] = { __byte_perm(w.w, 0, 0x1404), __byte_perm(w.w, 0, 0x3424) };
                    mma16816(D0[ng * 4 + 0], Ah0[kk], b0);  mma16816(D1[ng * 4 + 0], Ah1[kk], b0);
                    mma16816(D0[ng * 4 + 1], Ah0[kk], b1r); mma16816(D1[ng * 4 + 1], Ah1[kk], b1r);
                    mma16816(D0[ng * 4 + 2], Ah0[kk], b2r); mma16816(D1[ng * 4 + 2], Ah1[kk], b2r);
                    mma16816(D0[ng * 4 + 3], Ah0[kk], b3r); mma16816(D1[ng * 4 + 3], Ah1[kk], b3r);
                }
            }
            epilogue_hidden(D0, bs, q, Ah0);
            epilogue_hidden(D1, bs, q, Ah1);
        }

        // ---- layer 4 (head; W4 = hi + lo fp16) ----
        float D4a[2][4], D4b[2][4];
        #pragma unroll
        for (int f = 0; f < 2; f++)
            #pragma unroll
            for (int j = 0; j < 4; j++) { D4a[f][j] = 0.f; D4b[f][j] = 0.f; }
        #pragma unroll
        for (int kk = 0; kk < 8; kk++) {
            #pragma unroll
            for (int n = 0; n < 2; n++) {
                int ofs = ((kk * 16 + n * 8 + r) << 5) + q * 8;
                uint2 bhw = *(const uint2*)(smem + SM_W4HF + ofs);
                uint2 blw = *(const uint2*)(smem + SM_W4LF + ofs);
                uint32_t bh[2] = { bhw.x, bhw.y };
                uint32_t bl[2] = { blw.x, blw.y };
                mma16816(D4a[n], Ah0[kk], bh);
                mma16816(D4a[n], Ah0[kk], bl);
                mma16816(D4b[n], Ah1[kk], bh);
                mma16816(D4b[n], Ah1[kk], bl);
            }
        }

        // ---- output, both halves ----
        #pragma unroll
        for (int h = 0; h < 2; h++) {
            const float (*D4)[4] = (h == 0) ? D4a : D4b;
            float* o0 = out + (row0 + h * 16) * DOUT;
            float* o8 = o0 + (size_t)8 * DOUT;
            int cc = q * 2;
            float2 bb = *(const float2*)(b4s + cc);
            *(float2*)(o0 + cc) = make_float2(D4[0][0] + bb.x, D4[0][1] + bb.y);
            *(float2*)(o8 + cc) = make_float2(D4[0][2] + bb.x, D4[0][3] + bb.y);
            if (q == 0) {
                float2 b8 = *(const float2*)(b4s + 8);
                *(float2*)(o0 + 8) = make_float2(D4[1][0] + b8.x, D4[1][1] + b8.y);
                *(float2*)(o8 + 8) = make_float2(D4[1][2] + b8.x, D4[1][3] + b8.y);
            }
        }
    }
}

extern "C" void kernel_launch(void* const* d_in, const int* in_sizes, int n_in,
                              void* d_out, int out_size) {
    const float* x  = (const float*)d_in[0];
    const float* W1 = (const float*)d_in[1];
    const float* b1 = (const float*)d_in[2];
    const float* W2 = (const float*)d_in[3];
    const float* b2 = (const float*)d_in[4];
    const float* W3 = (const float*)d_in[5];
    const float* b3 = (const float*)d_in[6];
    const float* W4 = (const float*)d_in[7];
    const float* b4 = (const float*)d_in[8];
    float* out = (float*)d_out;

    int B = in_sizes[0] / DIN;
    int n_units = B / 32;

    static int configured = 0;
    if (!configured) {
        cudaFuncSetAttribute(bmlp_kernel, cudaFuncAttributeMaxDynamicSharedMemorySize, SM_TOTAL);
        configured = 1;
    }

    int grid = 152;
    int max_grid = (n_units + NWARP - 1) / NWARP;
    if (grid > max_grid) grid = max_grid;
    bmlp_kernel<<<grid, CTA_THREADS, SM_TOTAL>>>(x, W1, b1, W2, b2, W3, b3, W4, b4, out, n_units);
}

// round 6
// speedup vs baseline: 2.3550x; 1.1528x over previous
#include <cuda_runtime.h>
#include <cuda_fp16.h>
#include <cstdint>

// ============================================================
// BinaryMLP fused kernel (sm_103 virtual arch — portable mma.sync).
// R6: 32 rows/warp with Ah1 (second half activations) parked in
// warp-private smem scratch to eliminate the R5 register spills
// (regs 255->~210). B fragments still shared across both halves:
// 0.5 smem wavefront + 1 PRMT per HMMA. 8 warps/CTA, fp16
// single-pass, zero barriers in steady state.
// ============================================================

#define DIN   196
#define KPAD  208
#define HID   128
#define DOUT  10
#define NWARP 8
#define CTA_THREADS (NWARP * 32)

// ---- smem layout ----
#define SM_W1S  0                        // 13*4*512 = 26624
#define SM_W2S  (SM_W1S + 13*4*512)      // 8*4*512 = 16384
#define SM_W3S  (SM_W2S + 8*4*512)
#define SM_W4HF (SM_W3S + 8*4*512)       // fp16 frag blocks [8][16]*32 = 4096
#define SM_W4LF (SM_W4HF + 8*16*32)
#define SM_B1   (SM_W4LF + 8*16*32)
#define SM_B2   (SM_B1 + 512)
#define SM_B3   (SM_B2 + 512)
#define SM_B4   (SM_B3 + 512)
#define SM_AH1  (SM_B4 + 512)            // warp-private Ah1 scratch: 8 * 4096
#define SM_TOTAL (SM_AH1 + NWARP * 4096)

__device__ __forceinline__ int frag_off(int k) {
    return ((k & 7) >> 1) * 8 + ((k >> 3) & 1) * 4 + (k & 1) * 2;
}
__device__ __forceinline__ int sgn_addr(int n, int k) {
    int kk = k >> 4, nb = n >> 3, ng = nb >> 2, j = nb & 3;
    return ((kk * 4 + ng) << 9) + (((n & 7) * 4 + ((k & 7) >> 1)) << 4)
         + (j << 2) + (((k >> 3) & 1) << 1) + (k & 1);
}

__device__ __forceinline__ void mma16816(float* d, const uint32_t* a, const uint32_t* b) {
    asm volatile(
        "mma.sync.aligned.m16n8k16.row.col.f32.f16.f16.f32 "
        "{%0,%1,%2,%3},{%4,%5,%6,%7},{%8,%9},{%0,%1,%2,%3};"
        : "+f"(d[0]), "+f"(d[1]), "+f"(d[2]), "+f"(d[3])
        : "r"(a[0]), "r"(a[1]), "r"(a[2]), "r"(a[3]), "r"(b[0]), "r"(b[1]));
}

__device__ __forceinline__ uint32_t h2pack(float a, float b) {
    __half2 h = __floats2half2_rn(a, b);
    return *reinterpret_cast<uint32_t*>(&h);
}

// D -> +bias, ReLU, fp16 -> A fragments (register destination)
__device__ __forceinline__ void epilogue_reg(
    const float D[16][4], const float* bias, int q, uint32_t Ah[8][4])
{
    #pragma unroll
    for (int kk = 0; kk < 8; kk++) {
        const float* bp = bias + 16 * kk + q * 2;
        float2 b0 = *(const float2*)bp;
        float2 b1 = *(const float2*)(bp + 8);
        int f0 = 2 * kk, f1 = f0 + 1;
        Ah[kk][0] = h2pack(fmaxf(D[f0][0] + b0.x, 0.f), fmaxf(D[f0][1] + b0.y, 0.f));
        Ah[kk][1] = h2pack(fmaxf(D[f0][2] + b0.x, 0.f), fmaxf(D[f0][3] + b0.y, 0.f));
        Ah[kk][2] = h2pack(fmaxf(D[f1][0] + b1.x, 0.f), fmaxf(D[f1][1] + b1.y, 0.f));
        Ah[kk][3] = h2pack(fmaxf(D[f1][2] + b1.x, 0.f), fmaxf(D[f1][3] + b1.y, 0.f));
    }
}

// D -> +bias, ReLU, fp16 -> warp-private smem scratch (thread-private, no sync)
__device__ __forceinline__ void epilogue_smem(
    const float D[16][4], const float* bias, int q, char* dst)
{
    #pragma unroll
    for (int kk = 0; kk < 8; kk++) {
        const float* bp = bias + 16 * kk + q * 2;
        float2 b0 = *(const float2*)bp;
        float2 b1 = *(const float2*)(bp + 8);
        int f0 = 2 * kk, f1 = f0 + 1;
        uint32_t w0 = h2pack(fmaxf(D[f0][0] + b0.x, 0.f), fmaxf(D[f0][1] + b0.y, 0.f));
        uint32_t w1 = h2pack(fmaxf(D[f0][2] + b0.x, 0.f), fmaxf(D[f0][3] + b0.y, 0.f));
        uint32_t w2 = h2pack(fmaxf(D[f1][0] + b1.x, 0.f), fmaxf(D[f1][1] + b1.y, 0.f));
        uint32_t w3 = h2pack(fmaxf(D[f1][2] + b1.x, 0.f), fmaxf(D[f1][3] + b1.y, 0.f));
        *(uint4*)(dst + kk * 512) = make_uint4(w0, w1, w2, w3);
    }
}

__global__ void __launch_bounds__(CTA_THREADS, 1) bmlp_kernel(
    const float* __restrict__ x,
    const float* __restrict__ W1, const float* __restrict__ b1,
    const float* __restrict__ W2, const float* __restrict__ b2,
    const float* __restrict__ W3, const float* __restrict__ b3,
    const float* __restrict__ W4, const float* __restrict__ b4,
    float* __restrict__ out, int n_units)
{
    extern __shared__ char smem[];
    const int tid = threadIdx.x;
    const int lane = tid & 31;
    const int warp = tid >> 5;
    const int r = lane >> 2;
    const int q = lane & 3;

    // ---------------- prologue: weights -> smem ----------------
    for (int i = tid; i < HID * KPAD; i += CTA_THREADS) {
        int n = i / KPAD, k = i - n * KPAD;
        unsigned char s = 0;
        if (k < DIN) {
            float w = W1[n * DIN + k];
            s = (w > 0.f) ? 0x3Cu : ((w < 0.f) ? 0xBCu : 0u);
        }
        smem[SM_W1S + sgn_addr(n, k)] = s;
    }
    for (int i = tid; i < HID * HID; i += CTA_THREADS) {
        int n = i >> 7, k = i & 127;
        float w2 = W2[i], w3 = W3[i];
        unsigned char s2 = (w2 > 0.f) ? 0x3Cu : ((w2 < 0.f) ? 0xBCu : 0u);
        unsigned char s3 = (w3 > 0.f) ? 0x3Cu : ((w3 < 0.f) ? 0xBCu : 0u);
        int a = sgn_addr(n, k);
        smem[SM_W2S + a] = s2;
        smem[SM_W3S + a] = s3;
    }
    for (int i = tid; i < 16 * HID; i += CTA_THREADS) {
        int n = i >> 7, k = i & 127;
        float w = (n < DOUT) ? W4[n * HID + k] : 0.f;
        __half h = __float2half_rn(w);
        __half l = __float2half_rn(w - __half2float(h));
        int ofs = ((k >> 4) * 16 + n) * 32 + frag_off(k);
        *(unsigned short*)(smem + SM_W4HF + ofs) = __half_as_ushort(h);
        *(unsigned short*)(smem + SM_W4LF + ofs) = __half_as_ushort(l);
    }
    if (tid < HID) {
        ((float*)(smem + SM_B1))[tid] = b1[tid];
        ((float*)(smem + SM_B2))[tid] = b2[tid];
        ((float*)(smem + SM_B3))[tid] = b3[tid];
    }
    if (tid < 16) ((float*)(smem + SM_B4))[tid] = (tid < DOUT) ? b4[tid] : 0.f;
    __syncthreads();
    // Zero barriers after this point.

    const float* b1s = (const float*)(smem + SM_B1);
    const float* b2s = (const float*)(smem + SM_B2);
    const float* b3s = (const float*)(smem + SM_B3);
    const float* b4s = (const float*)(smem + SM_B4);
    char* ah1p = smem + SM_AH1 + warp * 4096 + lane * 16;   // thread-private scratch

    const int wstride = gridDim.x * NWARP;
    for (int c = blockIdx.x * NWARP + warp; c < n_units; c += wstride) {
        const size_t row0 = (size_t)c * 32 + r;
        const float* xa = x + row0 * DIN;
        const float* xb = xa + (size_t)8 * DIN;
        const float* xc = xa + (size_t)16 * DIN;
        const float* xd = xa + (size_t)24 * DIN;

        float D0[16][4], D1[16][4];
        #pragma unroll
        for (int f = 0; f < 16; f++)
            #pragma unroll
            for (int j = 0; j < 4; j++) { D0[f][j] = 0.f; D1[f][j] = 0.f; }

        // ---- layer 1 (K padded to 208) ----
        #pragma unroll
        for (int kk = 0; kk < 13; kk++) {
            int c0 = kk * 16 + q * 2;
            int c1 = c0 + 8;
            float2 z = make_float2(0.f, 0.f);
            float2 pa0 = (c0 < DIN) ? *(const float2*)(xa + c0) : z;
            float2 pb0 = (c0 < DIN) ? *(const float2*)(xb + c0) : z;
            float2 pc0 = (c0 < DIN) ? *(const float2*)(xc + c0) : z;
            float2 pd0 = (c0 < DIN) ? *(const float2*)(xd + c0) : z;
            float2 pa1 = (c1 < DIN) ? *(const float2*)(xa + c1) : z;
            float2 pb1 = (c1 < DIN) ? *(const float2*)(xb + c1) : z;
            float2 pc1 = (c1 < DIN) ? *(const float2*)(xc + c1) : z;
            float2 pd1 = (c1 < DIN) ? *(const float2*)(xd + c1) : z;
            uint32_t a0[4], a1[4];
            a0[0] = h2pack(pa0.x, pa0.y); a0[1] = h2pack(pb0.x, pb0.y);
            a0[2] = h2pack(pa1.x, pa1.y); a0[3] = h2pack(pb1.x, pb1.y);
            a1[0] = h2pack(pc0.x, pc0.y); a1[1] = h2pack(pd0.x, pd0.y);
            a1[2] = h2pack(pc1.x, pc1.y); a1[3] = h2pack(pd1.x, pd1.y);
            #pragma unroll
            for (int ng = 0; ng < 4; ng++) {
                uint4 w = *(const uint4*)(smem + SM_W1S + (((kk * 4 + ng) << 9) + lane * 16));
                uint32_t bw0[2] = { __byte_perm(w.x, 0, 0x1404), __byte_perm(w.x, 0, 0x3424) };
                uint32_t bw1[2] = { __byte_perm(w.y, 0, 0x1404), __byte_perm(w.y, 0, 0x3424) };
                uint32_t bw2[2] = { __byte_perm(w.z, 0, 0x1404), __byte_perm(w.z, 0, 0x3424) };
                uint32_t bw3[2] = { __byte_perm(w.w, 0, 0x1404), __byte_perm(w.w, 0, 0x3424) };
                mma16816(D0[ng * 4 + 0], a0, bw0); mma16816(D1[ng * 4 + 0], a1, bw0);
                mma16816(D0[ng * 4 + 1], a0, bw1); mma16816(D1[ng * 4 + 1], a1, bw1);
                mma16816(D0[ng * 4 + 2], a0, bw2); mma16816(D1[ng * 4 + 2], a1, bw2);
                mma16816(D0[ng * 4 + 3], a0, bw3); mma16816(D1[ng * 4 + 3], a1, bw3);
            }
        }

        uint32_t Ah0[8][4];
        epilogue_reg(D0, b1s, q, Ah0);
        epilogue_smem(D1, b1s, q, ah1p);

        // ---- layers 2 and 3 ----
        #pragma unroll
        for (int L = 0; L < 2; L++) {
            const char* Ws = (L == 0) ? (smem + SM_W2S) : (smem + SM_W3S);
            const float* bs = (L == 0) ? b2s : b3s;
            #pragma unroll
            for (int f = 0; f < 16; f++)
                #pragma unroll
                for (int j = 0; j < 4; j++) { D0[f][j] = 0.f; D1[f][j] = 0.f; }
            #pragma unroll
            for (int kk = 0; kk < 8; kk++) {
                uint4 av = *(const uint4*)(ah1p + kk * 512);
                uint32_t a1[4] = { av.x, av.y, av.z, av.w };
                #pragma unroll
                for (int ng = 0; ng < 4; ng++) {
                    uint4 w = *(const uint4*)(Ws + (((kk * 4 + ng) << 9) + lane * 16));
                    uint32_t bw0[2] = { __byte_perm(w.x, 0, 0x1404), __byte_perm(w.x, 0, 0x3424) };
                    uint32_t bw1[2] = { __byte_perm(w.y, 0, 0x1404), __byte_perm(w.y, 0, 0x3424) };
                    uint32_t bw2[2] = { __byte_perm(w.z, 0, 0x1404), __byte_perm(w.z, 0, 0x3424) };
                    uint32_t bw3[2] = { __byte_perm(w.w, 0, 0x1404), __byte_perm(w.w, 0, 0x3424) };
                    mma16816(D0[ng * 4 + 0], Ah0[kk], bw0); mma16816(D1[ng * 4 + 0], a1, bw0);
                    mma16816(D0[ng * 4 + 1], Ah0[kk], bw1); mma16816(D1[ng * 4 + 1], a1, bw1);
                    mma16816(D0[ng * 4 + 2], Ah0[kk], bw2); mma16816(D1[ng * 4 + 2], a1, bw2);
                    mma16816(D0[ng * 4 + 3], Ah0[kk], bw3); mma16816(D1[ng * 4 + 3], a1, bw3);
                }
            }
            epilogue_reg(D0, bs, q, Ah0);
            epilogue_smem(D1, bs, q, ah1p);
        }

        // ---- layer 4 (head; W4 = hi + lo fp16) ----
        float D4a[2][4], D4b[2][4];
        #pragma unroll
        for (int f = 0; f < 2; f++)
            #pragma unroll
            for (int j = 0; j < 4; j++) { D4a[f][j] = 0.f; D4b[f][j] = 0.f; }
        #pragma unroll
        for (int kk = 0; kk < 8; kk++) {
            uint4 av = *(const uint4*)(ah1p + kk * 512);
            uint32_t a1[4] = { av.x, av.y, av.z, av.w };
            #pragma unroll
            for (int n = 0; n < 2; n++) {
                int ofs = ((kk * 16 + n * 8 + r) << 5) + q * 8;
                uint2 bhw = *(const uint2*)(smem + SM_W4HF + ofs);
                uint2 blw = *(const uint2*)(smem + SM_W4LF + ofs);
                uint32_t bh[2] = { bhw.x, bhw.y };
                uint32_t bl[2] = { blw.x, blw.y };
                mma16816(D4a[n], Ah0[kk], bh);
                mma16816(D4a[n], Ah0[kk], bl);
                mma16816(D4b[n], a1, bh);
                mma16816(D4b[n], a1, bl);
            }
        }

        // ---- output, both halves ----
        #pragma unroll
        for (int h = 0; h < 2; h++) {
            const float (*D4)[4] = (h == 0) ? D4a : D4b;
            float* o0 = out + (row0 + h * 16) * DOUT;
            float* o8 = o0 + (size_t)8 * DOUT;
            int cc = q * 2;
            float2 bb = *(const float2*)(b4s + cc);
            *(float2*)(o0 + cc) = make_float2(D4[0][0] + bb.x, D4[0][1] + bb.y);
            *(float2*)(o8 + cc) = make_float2(D4[0][2] + bb.x, D4[0][3] + bb.y);
            if (q == 0) {
                float2 b8 = *(const float2*)(b4s + 8);
                *(float2*)(o0 + 8) = make_float2(D4[1][0] + b8.x, D4[1][1] + b8.y);
                *(float2*)(o8 + 8) = make_float2(D4[1][2] + b8.x, D4[1][3] + b8.y);
            }
        }
    }
}

extern "C" void kernel_launch(void* const* d_in, const int* in_sizes, int n_in,
                              void* d_out, int out_size) {
    const float* x  = (const float*)d_in[0];
    const float* W1 = (const float*)d_in[1];
    const float* b1 = (const float*)d_in[2];
    const float* W2 = (const float*)d_in[3];
    const float* b2 = (const float*)d_in[4];
    const float* W3 = (const float*)d_in[5];
    const float* b3 = (const float*)d_in[6];
    const float* W4 = (const float*)d_in[7];
    const float* b4 = (const float*)d_in[8];
    float* out = (float*)d_out;

    int B = in_sizes[0] / DIN;
    int n_units = B / 32;

    static int configured = 0;
    if (!configured) {
        cudaFuncSetAttribute(bmlp_kernel, cudaFuncAttributeMaxDynamicSharedMemorySize, SM_TOTAL);
        configured = 1;
    }

    int grid = 152;
    int max_grid = (n_units + NWARP - 1) / NWARP;
    if (grid > max_grid) grid = max_grid;
    bmlp_kernel<<<grid, CTA_THREADS, SM_TOTAL>>>(x, W1, b1, W2, b2, W3, b3, W4, b4, out, n_units);
}